// round 1
// baseline (speedup 1.0000x reference)
#include <cuda_runtime.h>

typedef unsigned long long ull;

#define HID 10
#define BATCH 16384
#define TPAIRS 1024
#define TPB 128

// ---------- packed fp32x2 helpers (sm_103a) ----------
__device__ __forceinline__ ull pack2(float lo, float hi){
    ull r; asm("mov.b64 %0, {%1, %2};" : "=l"(r) : "f"(lo), "f"(hi)); return r;
}
__device__ __forceinline__ ull bcast2(float v){
    ull r; asm("mov.b64 %0, {%1, %1};" : "=l"(r) : "f"(v)); return r;
}
__device__ __forceinline__ void unpack2(ull v, float &lo, float &hi){
    asm("mov.b64 {%0, %1}, %2;" : "=f"(lo), "=f"(hi) : "l"(v));
}
__device__ __forceinline__ ull ffma2(ull a, ull b, ull c){
    ull d; asm("fma.rn.f32x2 %0, %1, %2, %3;" : "=l"(d) : "l"(a), "l"(b), "l"(c)); return d;
}

// ---------- accurate fast activations (ex2.approx ~2ulp, rcp.approx ~1ulp) ----------
__device__ __forceinline__ float ex2f_(float x){ float r; asm("ex2.approx.f32 %0, %1;" : "=f"(r) : "f"(x)); return r; }
__device__ __forceinline__ float rcpf_(float x){ float r; asm("rcp.approx.f32 %0, %1;" : "=f"(r) : "f"(x)); return r; }
__device__ __forceinline__ float sigmoidf_(float x){
    // 1 / (1 + 2^(-x*log2e))
    return rcpf_(1.0f + ex2f_(x * -1.4426950408889634f));
}
__device__ __forceinline__ float tanhf_(float x){
    // 2*sigmoid(2x) - 1
    float s = rcpf_(1.0f + ex2f_(x * -2.8853900817779268f));
    return fmaf(2.0f, s, -1.0f);
}

// One LSTM cell step for one batch element (thread-private h/c, smem weights).
// wh: [HID][10] longlong2, each longlong2 = gates (4q..4q+3) weight pairs for h[j].
// NIN = number of input features (cellB: 1, cellA: 2).
template<int NIN>
__device__ __forceinline__ void cell_step(
    const longlong2* __restrict__ wh,    // 100 entries, [j*10+q]
    const longlong2* __restrict__ wx0,   // 10 entries
    const longlong2* __restrict__ wx1,   // 10 entries (unused if NIN==1)
    const longlong2* __restrict__ bias,  // 10 entries (bih+bhh fused)
    float h[HID], float c[HID], float x0, float x1)
{
    ull acc[20];
#pragma unroll
    for (int q = 0; q < 10; q++){
        longlong2 bq = bias[q];
        acc[2*q]   = (ull)bq.x;
        acc[2*q+1] = (ull)bq.y;
    }
    // recurrent part first: independent of x -> hides the x LDG latency
#pragma unroll
    for (int j = 0; j < HID; j++){
        ull hb = bcast2(h[j]);
#pragma unroll
        for (int q = 0; q < 10; q++){
            longlong2 w = wh[j*10 + q];
            acc[2*q]   = ffma2((ull)w.x, hb, acc[2*q]);
            acc[2*q+1] = ffma2((ull)w.y, hb, acc[2*q+1]);
        }
    }
    {
        ull xb = bcast2(x0);
#pragma unroll
        for (int q = 0; q < 10; q++){
            longlong2 w = wx0[q];
            acc[2*q]   = ffma2((ull)w.x, xb, acc[2*q]);
            acc[2*q+1] = ffma2((ull)w.y, xb, acc[2*q+1]);
        }
    }
    if (NIN == 2){
        ull xb = bcast2(x1);
#pragma unroll
        for (int q = 0; q < 10; q++){
            longlong2 w = wx1[q];
            acc[2*q]   = ffma2((ull)w.x, xb, acc[2*q]);
            acc[2*q+1] = ffma2((ull)w.y, xb, acc[2*q+1]);
        }
    }
    float g[40];
#pragma unroll
    for (int q = 0; q < 20; q++) unpack2(acc[q], g[2*q], g[2*q+1]);
    // PyTorch gate order: i, f, g, o
#pragma unroll
    for (int d = 0; d < HID; d++){
        float ig = sigmoidf_(g[d]);
        float fg = sigmoidf_(g[HID + d]);
        float gg = tanhf_(g[2*HID + d]);
        float og = sigmoidf_(g[3*HID + d]);
        float cn = fmaf(fg, c[d], ig * gg);
        c[d] = cn;
        h[d] = og * tanhf_(cn);
    }
}

__global__ void __launch_bounds__(TPB, 1)
multicell_lstm_kernel(
    const float* __restrict__ x,
    const float* __restrict__ WihA, const float* __restrict__ WhhA,
    const float* __restrict__ bihA, const float* __restrict__ bhhA,
    const float* __restrict__ WihB, const float* __restrict__ WhhB,
    const float* __restrict__ bihB, const float* __restrict__ bhhB,
    const float* __restrict__ Wlin, const float* __restrict__ blin,
    float* __restrict__ out)
{
    // packed weights in shared memory (per block, ~4KB)
    __shared__ longlong2 s_whA[100];
    __shared__ longlong2 s_whB[100];
    __shared__ longlong2 s_wxA0[10];
    __shared__ longlong2 s_wxA1[10];
    __shared__ longlong2 s_wxB0[10];
    __shared__ longlong2 s_bA[10];
    __shared__ longlong2 s_bB[10];

    const int tid = threadIdx.x;

    // Fill packed recurrent weights: s_wh[j*10+q] = pairs of gates (4q..4q+3) for h[j]
    for (int idx = tid; idx < 100; idx += TPB){
        int j = idx / 10, q = idx % 10;
        int g0 = 4 * q;
        s_whA[idx] = make_longlong2(
            (long long)pack2(WhhA[(g0+0)*HID + j], WhhA[(g0+1)*HID + j]),
            (long long)pack2(WhhA[(g0+2)*HID + j], WhhA[(g0+3)*HID + j]));
        s_whB[idx] = make_longlong2(
            (long long)pack2(WhhB[(g0+0)*HID + j], WhhB[(g0+1)*HID + j]),
            (long long)pack2(WhhB[(g0+2)*HID + j], WhhB[(g0+3)*HID + j]));
    }
    // Input weights + fused biases
    for (int q = tid; q < 10; q += TPB){
        int g0 = 4 * q;
        s_wxA0[q] = make_longlong2(
            (long long)pack2(WihA[(g0+0)*2 + 0], WihA[(g0+1)*2 + 0]),
            (long long)pack2(WihA[(g0+2)*2 + 0], WihA[(g0+3)*2 + 0]));
        s_wxA1[q] = make_longlong2(
            (long long)pack2(WihA[(g0+0)*2 + 1], WihA[(g0+1)*2 + 1]),
            (long long)pack2(WihA[(g0+2)*2 + 1], WihA[(g0+3)*2 + 1]));
        s_wxB0[q] = make_longlong2(
            (long long)pack2(WihB[g0+0], WihB[g0+1]),
            (long long)pack2(WihB[g0+2], WihB[g0+3]));
        s_bA[q] = make_longlong2(
            (long long)pack2(bihA[g0+0] + bhhA[g0+0], bihA[g0+1] + bhhA[g0+1]),
            (long long)pack2(bihA[g0+2] + bhhA[g0+2], bihA[g0+3] + bhhA[g0+3]));
        s_bB[q] = make_longlong2(
            (long long)pack2(bihB[g0+0] + bhhB[g0+0], bihB[g0+1] + bhhB[g0+1]),
            (long long)pack2(bihB[g0+2] + bhhB[g0+2], bihB[g0+3] + bhhB[g0+3]));
    }
    __syncthreads();

    const int b = blockIdx.x * TPB + tid;
    if (b >= BATCH) return;

    // x[b][t][k] at ((b*2048)+t)*2+k; one float4 per step-pair p:
    // (x[b,2p,0], x[b,2p,1], x[b,2p+1,0], x[b,2p+1,1]) -- 16B aligned
    const float4* xp = reinterpret_cast<const float4*>(x) + (size_t)b * TPAIRS;

    float h[HID], c[HID];
#pragma unroll
    for (int d = 0; d < HID; d++){ h[d] = 0.0f; c[d] = 0.0f; }

    for (int p = 0; p < TPAIRS; p++){
        float4 xv = __ldg(&xp[p]);
        // step 2p: cellB on x[:,2p,:1]
        cell_step<1>(s_whB, s_wxB0, s_wxB0, s_bB, h, c, xv.x, 0.0f);
        // step 2p+1: cellA on x[:,2p+1,:]
        cell_step<2>(s_whA, s_wxA0, s_wxA1, s_bA, h, c, xv.z, xv.w);
    }

    // out = sigmoid(h @ Wlin.T + blin)
    float a = __ldg(&blin[0]);
#pragma unroll
    for (int d = 0; d < HID; d++) a = fmaf(h[d], __ldg(&Wlin[d]), a);
    out[b] = sigmoidf_(a);
}

extern "C" void kernel_launch(void* const* d_in, const int* in_sizes, int n_in,
                              void* d_out, int out_size)
{
    const float* x    = (const float*)d_in[0];
    const float* WihA = (const float*)d_in[1];
    const float* WhhA = (const float*)d_in[2];
    const float* bihA = (const float*)d_in[3];
    const float* bhhA = (const float*)d_in[4];
    const float* WihB = (const float*)d_in[5];
    const float* WhhB = (const float*)d_in[6];
    const float* bihB = (const float*)d_in[7];
    const float* bhhB = (const float*)d_in[8];
    const float* Wlin = (const float*)d_in[9];
    const float* blin = (const float*)d_in[10];
    float* out = (float*)d_out;

    dim3 grid(BATCH / TPB), block(TPB);
    multicell_lstm_kernel<<<grid, block>>>(
        x, WihA, WhhA, bihA, bhhA, WihB, WhhB, bihB, bhhB, Wlin, blin, out);
}

// round 2
// speedup vs baseline: 1.5297x; 1.5297x over previous
#include <cuda_runtime.h>

typedef unsigned long long ull;

#define HID 10
#define BATCH 16384
#define TPAIRS 1024
#define TPB 128

// ---------- packed fp32x2 helpers (sm_103a) ----------
__device__ __forceinline__ ull pack2(float lo, float hi){
    ull r; asm("mov.b64 %0, {%1, %2};" : "=l"(r) : "f"(lo), "f"(hi)); return r;
}
__device__ __forceinline__ ull bcast2(float v){
    ull r; asm("mov.b64 %0, {%1, %1};" : "=l"(r) : "f"(v)); return r;
}
__device__ __forceinline__ void unpack2(ull v, float &lo, float &hi){
    asm("mov.b64 {%0, %1}, %2;" : "=f"(lo), "=f"(hi) : "l"(v));
}
__device__ __forceinline__ ull ffma2(ull a, ull b, ull c){
    ull d; asm("fma.rn.f32x2 %0, %1, %2, %3;" : "=l"(d) : "l"(a), "l"(b), "l"(c)); return d;
}

// ---------- HW tanh (MUFU.TANH, 1 MUFU op) ----------
__device__ __forceinline__ float tanh_ap(float x){
    float r; asm("tanh.approx.f32 %0, %1;" : "=f"(r) : "f"(x)); return r;
}

// One LSTM cell step for one batch element (thread-private h/c, smem weights).
// Weight rows for gates i (0..9), f (10..19), o (30..39) are PRE-SCALED by 0.5
// at smem-init time, so sigmoid(z) = 0.5*tanh(z/2)+0.5 needs only tanh + fma.
// Gate g rows (20..29) are unscaled (plain tanh).
// acc[2q] holds gates (4q, 4q+1), acc[2q+1] holds gates (4q+2, 4q+3).
template<int NIN>
__device__ __forceinline__ void cell_step(
    const longlong2* __restrict__ wh,    // 100 entries, [j*10+q]
    const longlong2* __restrict__ wx0,   // 10 entries
    const longlong2* __restrict__ wx1,   // 10 entries (unused if NIN==1)
    const longlong2* __restrict__ bias,  // 10 entries (bih+bhh fused, pre-scaled)
    float h[HID], float c[HID], float x0, float x1)
{
    ull acc[20];
#pragma unroll
    for (int q = 0; q < 10; q++){
        longlong2 bq = bias[q];
        acc[2*q]   = (ull)bq.x;
        acc[2*q+1] = (ull)bq.y;
    }
#pragma unroll
    for (int j = 0; j < HID; j++){
        ull hb = bcast2(h[j]);
#pragma unroll
        for (int q = 0; q < 10; q++){
            longlong2 w = wh[j*10 + q];
            acc[2*q]   = ffma2((ull)w.x, hb, acc[2*q]);
            acc[2*q+1] = ffma2((ull)w.y, hb, acc[2*q+1]);
        }
    }
    {
        ull xb = bcast2(x0);
#pragma unroll
        for (int q = 0; q < 10; q++){
            longlong2 w = wx0[q];
            acc[2*q]   = ffma2((ull)w.x, xb, acc[2*q]);
            acc[2*q+1] = ffma2((ull)w.y, xb, acc[2*q+1]);
        }
    }
    if (NIN == 2){
        ull xb = bcast2(x1);
#pragma unroll
        for (int q = 0; q < 10; q++){
            longlong2 w = wx1[q];
            acc[2*q]   = ffma2((ull)w.x, xb, acc[2*q]);
            acc[2*q+1] = ffma2((ull)w.y, xb, acc[2*q+1]);
        }
    }
    float g[40];
#pragma unroll
    for (int q = 0; q < 20; q++) unpack2(acc[q], g[2*q], g[2*q+1]);
    // gates: g[0..9]=i' (half-scaled), g[10..19]=f' (half-scaled),
    //        g[20..29]=g (unscaled), g[30..39]=o' (half-scaled)
#pragma unroll
    for (int d = 0; d < HID; d++){
        float si = fmaf(0.5f, tanh_ap(g[d]),        0.5f);
        float sf = fmaf(0.5f, tanh_ap(g[HID + d]),  0.5f);
        float tg = tanh_ap(g[2*HID + d]);
        float so = fmaf(0.5f, tanh_ap(g[3*HID + d]),0.5f);
        float cn = fmaf(sf, c[d], si * tg);
        c[d] = cn;
        h[d] = so * tanh_ap(cn);
    }
}

__global__ void __launch_bounds__(TPB, 1)
multicell_lstm_kernel(
    const float* __restrict__ x,
    const float* __restrict__ WihA, const float* __restrict__ WhhA,
    const float* __restrict__ bihA, const float* __restrict__ bhhA,
    const float* __restrict__ WihB, const float* __restrict__ WhhB,
    const float* __restrict__ bihB, const float* __restrict__ bhhB,
    const float* __restrict__ Wlin, const float* __restrict__ blin,
    float* __restrict__ out)
{
    __shared__ longlong2 s_whA[100];
    __shared__ longlong2 s_whB[100];
    __shared__ longlong2 s_wxA0[10];
    __shared__ longlong2 s_wxA1[10];
    __shared__ longlong2 s_wxB0[10];
    __shared__ longlong2 s_bA[10];
    __shared__ longlong2 s_bB[10];

    const int tid = threadIdx.x;

    // 0.5 folding: gate rows i (0..9), f (10..19), o (30..39) scaled by 0.5;
    // g rows (20..29) unscaled.
    // s_wh[j*10+q] = pairs of gates (4q..4q+3) for h[j]
    for (int idx = tid; idx < 100; idx += TPB){
        int j = idx / 10, q = idx % 10;
        int g0 = 4 * q;
        float s0 = (g0+0 >= 20 && g0+0 < 30) ? 1.0f : 0.5f;
        float s1 = (g0+1 >= 20 && g0+1 < 30) ? 1.0f : 0.5f;
        float s2 = (g0+2 >= 20 && g0+2 < 30) ? 1.0f : 0.5f;
        float s3 = (g0+3 >= 20 && g0+3 < 30) ? 1.0f : 0.5f;
        s_whA[idx] = make_longlong2(
            (long long)pack2(s0*WhhA[(g0+0)*HID + j], s1*WhhA[(g0+1)*HID + j]),
            (long long)pack2(s2*WhhA[(g0+2)*HID + j], s3*WhhA[(g0+3)*HID + j]));
        s_whB[idx] = make_longlong2(
            (long long)pack2(s0*WhhB[(g0+0)*HID + j], s1*WhhB[(g0+1)*HID + j]),
            (long long)pack2(s2*WhhB[(g0+2)*HID + j], s3*WhhB[(g0+3)*HID + j]));
    }
    for (int q = tid; q < 10; q += TPB){
        int g0 = 4 * q;
        float s0 = (g0+0 >= 20 && g0+0 < 30) ? 1.0f : 0.5f;
        float s1 = (g0+1 >= 20 && g0+1 < 30) ? 1.0f : 0.5f;
        float s2 = (g0+2 >= 20 && g0+2 < 30) ? 1.0f : 0.5f;
        float s3 = (g0+3 >= 20 && g0+3 < 30) ? 1.0f : 0.5f;
        s_wxA0[q] = make_longlong2(
            (long long)pack2(s0*WihA[(g0+0)*2 + 0], s1*WihA[(g0+1)*2 + 0]),
            (long long)pack2(s2*WihA[(g0+2)*2 + 0], s3*WihA[(g0+3)*2 + 0]));
        s_wxA1[q] = make_longlong2(
            (long long)pack2(s0*WihA[(g0+0)*2 + 1], s1*WihA[(g0+1)*2 + 1]),
            (long long)pack2(s2*WihA[(g0+2)*2 + 1], s3*WihA[(g0+3)*2 + 1]));
        s_wxB0[q] = make_longlong2(
            (long long)pack2(s0*WihB[g0+0], s1*WihB[g0+1]),
            (long long)pack2(s2*WihB[g0+2], s3*WihB[g0+3]));
        s_bA[q] = make_longlong2(
            (long long)pack2(s0*(bihA[g0+0] + bhhA[g0+0]), s1*(bihA[g0+1] + bhhA[g0+1])),
            (long long)pack2(s2*(bihA[g0+2] + bhhA[g0+2]), s3*(bihA[g0+3] + bhhA[g0+3])));
        s_bB[q] = make_longlong2(
            (long long)pack2(s0*(bihB[g0+0] + bhhB[g0+0]), s1*(bihB[g0+1] + bhhB[g0+1])),
            (long long)pack2(s2*(bihB[g0+2] + bhhB[g0+2]), s3*(bihB[g0+3] + bhhB[g0+3])));
    }
    __syncthreads();

    const int b = blockIdx.x * TPB + tid;
    if (b >= BATCH) return;

    const float4* xp = reinterpret_cast<const float4*>(x) + (size_t)b * TPAIRS;

    float h[HID], c[HID];
#pragma unroll
    for (int d = 0; d < HID; d++){ h[d] = 0.0f; c[d] = 0.0f; }

    for (int p = 0; p < TPAIRS; p++){
        float4 xv = __ldg(&xp[p]);
        cell_step<1>(s_whB, s_wxB0, s_wxB0, s_bB, h, c, xv.x, 0.0f);
        cell_step<2>(s_whA, s_wxA0, s_wxA1, s_bA, h, c, xv.z, xv.w);
    }

    // out = sigmoid(h @ Wlin.T + blin) = 0.5*tanh(0.5*(...)) + 0.5
    float a = __ldg(&blin[0]);
#pragma unroll
    for (int d = 0; d < HID; d++) a = fmaf(h[d], __ldg(&Wlin[d]), a);
    out[b] = fmaf(0.5f, tanh_ap(0.5f * a), 0.5f);
}

extern "C" void kernel_launch(void* const* d_in, const int* in_sizes, int n_in,
                              void* d_out, int out_size)
{
    const float* x    = (const float*)d_in[0];
    const float* WihA = (const float*)d_in[1];
    const float* WhhA = (const float*)d_in[2];
    const float* bihA = (const float*)d_in[3];
    const float* bhhA = (const float*)d_in[4];
    const float* WihB = (const float*)d_in[5];
    const float* WhhB = (const float*)d_in[6];
    const float* bihB = (const float*)d_in[7];
    const float* bhhB = (const float*)d_in[8];
    const float* Wlin = (const float*)d_in[9];
    const float* blin = (const float*)d_in[10];
    float* out = (float*)d_out;

    dim3 grid(BATCH / TPB), block(TPB);
    multicell_lstm_kernel<<<grid, block>>>(
        x, WihA, WhhA, bihA, bhhA, WihB, WhhB, bihB, bhhB, Wlin, blin, out);
}

// round 3
// speedup vs baseline: 1.5530x; 1.0152x over previous
#include <cuda_runtime.h>

typedef unsigned long long ull;

#define HID 10
#define BATCH 16384
#define TPAIRS 1024
#define TPB 128

// ---------- packed fp32x2 helpers (sm_103a) ----------
__device__ __forceinline__ ull pack2(float lo, float hi){
    ull r; asm("mov.b64 %0, {%1, %2};" : "=l"(r) : "f"(lo), "f"(hi)); return r;
}
__device__ __forceinline__ ull bcast2(float v){
    ull r; asm("mov.b64 %0, {%1, %1};" : "=l"(r) : "f"(v)); return r;
}
__device__ __forceinline__ void unpack2(ull v, float &lo, float &hi){
    asm("mov.b64 {%0, %1}, %2;" : "=f"(lo), "=f"(hi) : "l"(v));
}
__device__ __forceinline__ ull ffma2(ull a, ull b, ull c){
    ull d; asm("fma.rn.f32x2 %0, %1, %2, %3;" : "=l"(d) : "l"(a), "l"(b), "l"(c)); return d;
}

// ---------- HW tanh (MUFU.TANH, 1 MUFU op) ----------
__device__ __forceinline__ float tanh_ap(float x){
    float r; asm("tanh.approx.f32 %0, %1;" : "=f"(r) : "f"(x)); return r;
}

// 2 threads per element. Thread r (= tid&1) owns dims d = 5r..5r+4 and computes
// all 4 gates for those dims. Gate rows i/f/o pre-scaled by 0.5 (sigmoid via
// 0.5*tanh(z/2)+0.5); g rows unscaled.
// acc packing per owned dim p: aIF[p] = (i_d, f_d), aGO[p] = (g_d, o_d).
// wh layout: [jj*10 + r*5 + p] longlong2, where jj 0..4 = this thread's own
// dims (actual j = 5r+jj) and jj 5..9 = partner dims (actual j = 5(1-r)+jj-5),
// so both threads walk own-h first, then shfl-received partner-h.
template<int NIN>
__device__ __forceinline__ void cell_step2(
    const longlong2* __restrict__ wh,    // 100 entries
    const longlong2* __restrict__ wx0,   // 10 entries [r*5+p]
    const longlong2* __restrict__ wx1,   // 10 entries (NIN==2 only)
    const longlong2* __restrict__ bias,  // 10 entries [r*5+p]
    int rbase, float h[5], float c[5], float x0, float x1)
{
    // exchange partner h first -> 26cyc shfl latency hides under own-dims matvec
    float hp[5];
#pragma unroll
    for (int p = 0; p < 5; p++) hp[p] = __shfl_xor_sync(0xffffffffu, h[p], 1);

    ull aIF[5], aGO[5];
#pragma unroll
    for (int p = 0; p < 5; p++){
        longlong2 b = bias[rbase + p];
        aIF[p] = (ull)b.x; aGO[p] = (ull)b.y;
    }
    {
        ull xb = bcast2(x0);
#pragma unroll
        for (int p = 0; p < 5; p++){
            longlong2 w = wx0[rbase + p];
            aIF[p] = ffma2((ull)w.x, xb, aIF[p]);
            aGO[p] = ffma2((ull)w.y, xb, aGO[p]);
        }
    }
    if (NIN == 2){
        ull xb = bcast2(x1);
#pragma unroll
        for (int p = 0; p < 5; p++){
            longlong2 w = wx1[rbase + p];
            aIF[p] = ffma2((ull)w.x, xb, aIF[p]);
            aGO[p] = ffma2((ull)w.y, xb, aGO[p]);
        }
    }
    // own dims
#pragma unroll
    for (int jj = 0; jj < 5; jj++){
        ull hb = bcast2(h[jj]);
#pragma unroll
        for (int p = 0; p < 5; p++){
            longlong2 w = wh[jj*10 + rbase + p];
            aIF[p] = ffma2((ull)w.x, hb, aIF[p]);
            aGO[p] = ffma2((ull)w.y, hb, aGO[p]);
        }
    }
    // partner dims
#pragma unroll
    for (int jj = 0; jj < 5; jj++){
        ull hb = bcast2(hp[jj]);
#pragma unroll
        for (int p = 0; p < 5; p++){
            longlong2 w = wh[(jj+5)*10 + rbase + p];
            aIF[p] = ffma2((ull)w.x, hb, aIF[p]);
            aGO[p] = ffma2((ull)w.y, hb, aGO[p]);
        }
    }
    // epilogue: 5 MUFU per owned dim
#pragma unroll
    for (int p = 0; p < 5; p++){
        float zi, zf, zg, zo;
        unpack2(aIF[p], zi, zf);
        unpack2(aGO[p], zg, zo);
        float si = fmaf(0.5f, tanh_ap(zi), 0.5f);
        float sf = fmaf(0.5f, tanh_ap(zf), 0.5f);
        float tg = tanh_ap(zg);
        float so = fmaf(0.5f, tanh_ap(zo), 0.5f);
        float cn = fmaf(sf, c[p], si * tg);
        c[p] = cn;
        h[p] = so * tanh_ap(cn);
    }
}

__global__ void __launch_bounds__(TPB, 2)
multicell_lstm_kernel(
    const float* __restrict__ x,
    const float* __restrict__ WihA, const float* __restrict__ WhhA,
    const float* __restrict__ bihA, const float* __restrict__ bhhA,
    const float* __restrict__ WihB, const float* __restrict__ WhhB,
    const float* __restrict__ bihB, const float* __restrict__ bhhB,
    const float* __restrict__ Wlin, const float* __restrict__ blin,
    float* __restrict__ out)
{
    __shared__ longlong2 s_whB[100];
    __shared__ longlong2 s_whA[100];
    __shared__ longlong2 s_wxB[10];
    __shared__ longlong2 s_wxA0[10];
    __shared__ longlong2 s_wxA1[10];
    __shared__ longlong2 s_bB[10];
    __shared__ longlong2 s_bA[10];

    const int tid = threadIdx.x;

    // recurrent weights, both cells: 200 longlong2 entries
    for (int idx = tid; idx < 200; idx += TPB){
        int cell = idx / 100;           // 0 = B, 1 = A
        int rem  = idx % 100;           // jj*10 + r*5 + p
        int jj = rem / 10;
        int r  = (rem % 10) / 5;
        int p  = rem % 5;
        int aj = (jj < 5) ? (5*r + jj) : (5*(1-r) + (jj-5));
        int d  = 5*r + p;
        const float* W = cell ? WhhA : WhhB;
        longlong2 v = make_longlong2(
            (long long)pack2(0.5f*W[(      d)*HID + aj], 0.5f*W[(  HID+d)*HID + aj]),
            (long long)pack2(     W[(2*HID+d)*HID + aj], 0.5f*W[(3*HID+d)*HID + aj]));
        if (cell) s_whA[rem] = v; else s_whB[rem] = v;
    }
    // input weights + fused biases: indexed [r*5+p], d = 5r+p
    for (int idx = tid; idx < 10; idx += TPB){
        int r = idx / 5, p = idx % 5;
        int d = 5*r + p;
        s_wxB[idx] = make_longlong2(
            (long long)pack2(0.5f*WihB[d],        0.5f*WihB[HID+d]),
            (long long)pack2(     WihB[2*HID+d],  0.5f*WihB[3*HID+d]));
        s_wxA0[idx] = make_longlong2(
            (long long)pack2(0.5f*WihA[(      d)*2], 0.5f*WihA[(  HID+d)*2]),
            (long long)pack2(     WihA[(2*HID+d)*2], 0.5f*WihA[(3*HID+d)*2]));
        s_wxA1[idx] = make_longlong2(
            (long long)pack2(0.5f*WihA[(      d)*2+1], 0.5f*WihA[(  HID+d)*2+1]),
            (long long)pack2(     WihA[(2*HID+d)*2+1], 0.5f*WihA[(3*HID+d)*2+1]));
        s_bB[idx] = make_longlong2(
            (long long)pack2(0.5f*(bihB[d]       + bhhB[d]),
                             0.5f*(bihB[HID+d]   + bhhB[HID+d])),
            (long long)pack2(     (bihB[2*HID+d] + bhhB[2*HID+d]),
                             0.5f*(bihB[3*HID+d] + bhhB[3*HID+d])));
        s_bA[idx] = make_longlong2(
            (long long)pack2(0.5f*(bihA[d]       + bhhA[d]),
                             0.5f*(bihA[HID+d]   + bhhA[HID+d])),
            (long long)pack2(     (bihA[2*HID+d] + bhhA[2*HID+d]),
                             0.5f*(bihA[3*HID+d] + bhhA[3*HID+d])));
    }
    __syncthreads();

    const int gtid  = blockIdx.x * TPB + tid;
    const int e     = gtid >> 1;          // element id, 2 threads per element
    const int rbase = (tid & 1) * 5;      // owned-dim base

    const float4* xp = reinterpret_cast<const float4*>(x) + (size_t)e * TPAIRS;

    float h[5], c[5];
#pragma unroll
    for (int p = 0; p < 5; p++){ h[p] = 0.0f; c[p] = 0.0f; }

    for (int p = 0; p < TPAIRS; p++){
        float4 xv = __ldg(&xp[p]);
        cell_step2<1>(s_whB, s_wxB,  s_wxB,  s_bB, rbase, h, c, xv.x, 0.0f);
        cell_step2<2>(s_whA, s_wxA0, s_wxA1, s_bA, rbase, h, c, xv.z, xv.w);
    }

    // out = sigmoid(h @ Wlin.T + blin): partial dot over owned dims + pair-sum
    float a = 0.0f;
#pragma unroll
    for (int p = 0; p < 5; p++) a = fmaf(h[p], __ldg(&Wlin[rbase + p]), a);
    a += __shfl_xor_sync(0xffffffffu, a, 1);
    if ((tid & 1) == 0)
        out[e] = fmaf(0.5f, tanh_ap(0.5f * (a + __ldg(&blin[0]))), 0.5f);
}

extern "C" void kernel_launch(void* const* d_in, const int* in_sizes, int n_in,
                              void* d_out, int out_size)
{
    const float* x    = (const float*)d_in[0];
    const float* WihA = (const float*)d_in[1];
    const float* WhhA = (const float*)d_in[2];
    const float* bihA = (const float*)d_in[3];
    const float* bhhA = (const float*)d_in[4];
    const float* WihB = (const float*)d_in[5];
    const float* WhhB = (const float*)d_in[6];
    const float* bihB = (const float*)d_in[7];
    const float* bhhB = (const float*)d_in[8];
    const float* Wlin = (const float*)d_in[9];
    const float* blin = (const float*)d_in[10];
    float* out = (float*)d_out;

    dim3 grid((BATCH * 2) / TPB), block(TPB);   // 256 blocks, 2 threads/element
    multicell_lstm_kernel<<<grid, block>>>(
        x, WihA, WhhA, bihA, bhhA, WihB, WhhB, bihB, bhhB, Wlin, blin, out);
}